// round 4
// baseline (speedup 1.0000x reference)
#include <cuda_runtime.h>

#define N_NODES 50000
#define N_EDGES 600000
#define DIM 128
#define TOT_EDGES (N_EDGES + N_NODES)   // edges + self loops

// ---- scratch (device globals; no allocations allowed) ----
__device__ float g_hw [N_NODES * DIM];   // h @ W
__device__ float g_agg[N_NODES * DIM];   // scatter accumulator (init to bias)
__device__ float g_dinv[N_NODES];        // deg, then rsqrt(deg) in place

// ---------------------------------------------------------------------------
// degree: init to 1.0 (self loop), count dst occurrences, then rsqrt in place
// ---------------------------------------------------------------------------
__global__ void deg_init_k() {
    int i = blockIdx.x * blockDim.x + threadIdx.x;
    if (i < N_NODES) g_dinv[i] = 1.0f;
}

__global__ void deg_count_k(const int* __restrict__ ei) {
    int e = blockIdx.x * blockDim.x + threadIdx.x;
    if (e < N_EDGES) {
        int d = ei[N_EDGES + e];   // dst row of edge_index (int32)
        if (d >= 0 && d < N_NODES)
            atomicAdd(&g_dinv[d], 1.0f);
    }
}

__global__ void dinv_k() {
    int i = blockIdx.x * blockDim.x + threadIdx.x;
    if (i < N_NODES) g_dinv[i] = rsqrtf(g_dinv[i]);
}

// ---------------------------------------------------------------------------
// GEMM: g_hw[N,128] = src @ W[128,128]
//   src = external A (use_agg=0, no relu) or relu(g_agg) (use_agg=1)
// 128x128 block tile, BK=16, 8x8 per thread, 256 threads
// ---------------------------------------------------------------------------
__global__ void __launch_bounds__(256) gemm_relu_k(
    const float* __restrict__ A, const float* __restrict__ W, int use_agg)
{
    __shared__ float As[16][128];   // [k][row]  (A transposed in smem)
    __shared__ float Bs[16][128];   // [k][col]

    const int tid  = threadIdx.x;
    const int row0 = blockIdx.x * 128;
    const int trow = (tid >> 4) * 8;   // 0..120
    const int tcol = (tid & 15) * 8;   // 0..120

    const float* src = use_agg ? g_agg : A;

    float acc[8][8];
#pragma unroll
    for (int m = 0; m < 8; m++)
#pragma unroll
        for (int n = 0; n < 8; n++) acc[m][n] = 0.0f;

    for (int k0 = 0; k0 < 128; k0 += 16) {
        // load A tile: 128 rows x 16 cols = 512 float4, 2 per thread
#pragma unroll
        for (int t = 0; t < 2; t++) {
            int i  = tid + t * 256;
            int r  = i >> 2;           // 0..127
            int c4 = (i & 3) * 4;      // 0,4,8,12
            int grow = row0 + r;
            float4 v = make_float4(0.f, 0.f, 0.f, 0.f);
            if (grow < N_NODES)
                v = *(const float4*)(src + (size_t)grow * DIM + k0 + c4);
            if (use_agg) {
                v.x = fmaxf(v.x, 0.f); v.y = fmaxf(v.y, 0.f);
                v.z = fmaxf(v.z, 0.f); v.w = fmaxf(v.w, 0.f);
            }
            As[c4 + 0][r] = v.x; As[c4 + 1][r] = v.y;
            As[c4 + 2][r] = v.z; As[c4 + 3][r] = v.w;
        }
        // load B tile: 16 rows x 128 cols = 512 float4, 2 per thread
#pragma unroll
        for (int t = 0; t < 2; t++) {
            int i = tid + t * 256;
            int r = i >> 5;            // 0..15
            int c = (i & 31) * 4;      // 0..124
            *(float4*)&Bs[r][c] = *(const float4*)(W + (size_t)(k0 + r) * DIM + c);
        }
        __syncthreads();

#pragma unroll
        for (int k = 0; k < 16; k++) {
            float a[8], b[8];
#pragma unroll
            for (int m = 0; m < 8; m++) a[m] = As[k][trow + m];
#pragma unroll
            for (int n = 0; n < 8; n++) b[n] = Bs[k][tcol + n];
#pragma unroll
            for (int m = 0; m < 8; m++)
#pragma unroll
                for (int n = 0; n < 8; n++)
                    acc[m][n] += a[m] * b[n];
        }
        __syncthreads();
    }

#pragma unroll
    for (int m = 0; m < 8; m++) {
        int grow = row0 + trow + m;
        if (grow < N_NODES) {
#pragma unroll
            for (int n = 0; n < 8; n += 4) {
                float4 v = make_float4(acc[m][n], acc[m][n + 1],
                                       acc[m][n + 2], acc[m][n + 3]);
                *(float4*)(g_hw + (size_t)grow * DIM + tcol + n) = v;
            }
        }
    }
}

// ---------------------------------------------------------------------------
// init accumulator to bias (broadcast b over all rows)
// ---------------------------------------------------------------------------
__global__ void bias_init_k(const float* __restrict__ b) {
    int i = blockIdx.x * blockDim.x + threadIdx.x;   // float4 index
    if (i < N_NODES * DIM / 4) {
        const float4* b4 = (const float4*)b;
        ((float4*)g_agg)[i] = b4[i & 31];            // 128/4 = 32 float4 per row
    }
}

// ---------------------------------------------------------------------------
// scatter: one warp per (edge or self-loop); lane handles 4 floats
// agg[dst] += hw[src] * dinv[src]*dinv[dst]
// ---------------------------------------------------------------------------
__global__ void __launch_bounds__(128) scatter_k(const int* __restrict__ ei) {
    int gw   = (blockIdx.x * blockDim.x + threadIdx.x) >> 5;   // global warp id
    int lane = threadIdx.x & 31;
    if (gw >= TOT_EDGES) return;

    int s, d;
    if (gw < N_EDGES) {
        s = ei[gw];
        d = ei[N_EDGES + gw];
        if (s < 0 || s >= N_NODES || d < 0 || d >= N_NODES) return;  // safety
    } else {
        s = d = gw - N_EDGES;   // self loop
    }
    float nrm = g_dinv[s] * g_dinv[d];

    float4 v = *(const float4*)(g_hw + (size_t)s * DIM + lane * 4);
    float* dp = g_agg + (size_t)d * DIM + lane * 4;
    atomicAdd(dp + 0, v.x * nrm);
    atomicAdd(dp + 1, v.y * nrm);
    atomicAdd(dp + 2, v.z * nrm);
    atomicAdd(dp + 3, v.w * nrm);
}

// ---------------------------------------------------------------------------
// final relu into d_out
// ---------------------------------------------------------------------------
__global__ void relu_out_k(float* __restrict__ out) {
    int i = blockIdx.x * blockDim.x + threadIdx.x;   // float4 index
    if (i < N_NODES * DIM / 4) {
        float4 v = ((const float4*)g_agg)[i];
        v.x = fmaxf(v.x, 0.f); v.y = fmaxf(v.y, 0.f);
        v.z = fmaxf(v.z, 0.f); v.w = fmaxf(v.w, 0.f);
        ((float4*)out)[i] = v;
    }
}

// ---------------------------------------------------------------------------
extern "C" void kernel_launch(void* const* d_in, const int* in_sizes, int n_in,
                              void* d_out, int out_size)
{
    const float* x  = (const float*)d_in[0];
    const int*   ei = (const int*)d_in[1];     // edge_index as int32 [2, E]
    const float* W0 = (const float*)d_in[2];
    const float* b0 = (const float*)d_in[3];
    const float* W1 = (const float*)d_in[4];
    const float* b1 = (const float*)d_in[5];
    const float* W2 = (const float*)d_in[6];
    const float* b2 = (const float*)d_in[7];
    float* out = (float*)d_out;

    const int nodeBlocks  = (N_NODES + 255) / 256;
    const int edgeBlocks  = (N_EDGES + 255) / 256;
    const int gemmBlocks  = (N_NODES + 127) / 128;
    const int featBlocks  = (N_NODES * DIM / 4 + 255) / 256;
    const int scatBlocks  = (TOT_EDGES * 32 + 127) / 128;

    // normalization
    deg_init_k <<<nodeBlocks, 256>>>();
    deg_count_k<<<edgeBlocks, 256>>>(ei);
    dinv_k     <<<nodeBlocks, 256>>>();

    // layer 0: hw = x @ W0 ; agg = b0 ; agg += scatter
    gemm_relu_k<<<gemmBlocks, 256>>>(x, W0, 0);
    bias_init_k<<<featBlocks, 256>>>(b0);
    scatter_k  <<<scatBlocks, 128>>>(ei);

    // layer 1: hw = relu(agg) @ W1 ; agg = b1 ; agg += scatter
    gemm_relu_k<<<gemmBlocks, 256>>>(x, W1, 1);
    bias_init_k<<<featBlocks, 256>>>(b1);
    scatter_k  <<<scatBlocks, 128>>>(ei);

    // layer 2: hw = relu(agg) @ W2 ; agg = b2 ; agg += scatter
    gemm_relu_k<<<gemmBlocks, 256>>>(x, W2, 1);
    bias_init_k<<<featBlocks, 256>>>(b2);
    scatter_k  <<<scatBlocks, 128>>>(ei);

    // out = relu(agg)
    relu_out_k<<<featBlocks, 256>>>(out);
}

// round 6
// speedup vs baseline: 2.7653x; 2.7653x over previous
#include <cuda_runtime.h>

#define N_NODES 50000
#define N_EDGES 600000
#define DIM 128
#define TOT_EDGES (N_EDGES + N_NODES)   // edges + self loops
#define NB 196                          // ceil(50000/256) scan blocks

// ---- scratch (device globals; no allocations allowed) ----
__device__ float g_hw  [N_NODES * DIM];  // h @ W
__device__ float g_agg [N_NODES * DIM];  // layer output (agg + b)
__device__ float g_dinv[N_NODES];        // rsqrt(deg)
__device__ int   g_deg   [N_NODES];
__device__ int   g_rowptr[N_NODES + 1];
__device__ int   g_cursor[N_NODES];
__device__ int   g_bsum  [NB];
__device__ int   g_esrc  [TOT_EDGES];    // CSR-by-dst: src node per slot
__device__ float g_enorm [TOT_EDGES];    // dinv[src]*dinv[dst] per slot

// ---------------------------------------------------------------------------
// CSR build: degree -> scan -> rowptr/cursor/dinv -> fill
// ---------------------------------------------------------------------------
__global__ void deg_init_k() {
    int i = blockIdx.x * blockDim.x + threadIdx.x;
    if (i < N_NODES) g_deg[i] = 1;          // self loop
}

__global__ void deg_count_k(const int* __restrict__ ei) {
    int e = blockIdx.x * blockDim.x + threadIdx.x;
    if (e < N_EDGES) {
        int d = ei[N_EDGES + e];
        if (d >= 0 && d < N_NODES) atomicAdd(&g_deg[d], 1);
    }
}

__global__ void __launch_bounds__(256) bsum_k() {
    __shared__ int sh[256];
    int i = blockIdx.x * 256 + threadIdx.x;
    sh[threadIdx.x] = (i < N_NODES) ? g_deg[i] : 0;
    __syncthreads();
    for (int off = 128; off > 0; off >>= 1) {
        if (threadIdx.x < off) sh[threadIdx.x] += sh[threadIdx.x + off];
        __syncthreads();
    }
    if (threadIdx.x == 0) g_bsum[blockIdx.x] = sh[0];
}

__global__ void __launch_bounds__(256) topscan_k() {   // exclusive scan of g_bsum
    __shared__ int sh[256];
    int t = threadIdx.x;
    int v = (t < NB) ? g_bsum[t] : 0;
    sh[t] = v;
    __syncthreads();
    for (int off = 1; off < 256; off <<= 1) {
        int x = (t >= off) ? sh[t - off] : 0;
        __syncthreads();
        sh[t] += x;
        __syncthreads();
    }
    if (t < NB) g_bsum[t] = sh[t] - v;      // exclusive
}

__global__ void __launch_bounds__(256) finalize_k() {
    __shared__ int sh[256];
    int i = blockIdx.x * 256 + threadIdx.x;
    int t = threadIdx.x;
    int v = (i < N_NODES) ? g_deg[i] : 0;
    sh[t] = v;
    __syncthreads();
    for (int off = 1; off < 256; off <<= 1) {
        int x = (t >= off) ? sh[t - off] : 0;
        __syncthreads();
        sh[t] += x;
        __syncthreads();
    }
    if (i < N_NODES) {
        int start = g_bsum[blockIdx.x] + sh[t] - v;   // exclusive global
        g_rowptr[i] = start;
        g_cursor[i] = start;
        g_dinv[i]   = rsqrtf((float)v);
        if (i == N_NODES - 1) g_rowptr[N_NODES] = start + v;
    }
}

__global__ void fill_k(const int* __restrict__ ei) {
    int e = blockIdx.x * blockDim.x + threadIdx.x;
    if (e >= TOT_EDGES) return;
    int s, d;
    if (e < N_EDGES) {
        s = ei[e];
        d = ei[N_EDGES + e];
        if (s < 0 || s >= N_NODES || d < 0 || d >= N_NODES) return;
    } else {
        s = d = e - N_EDGES;                // self loop
    }
    int pos = atomicAdd(&g_cursor[d], 1);
    g_esrc[pos]  = s;
    g_enorm[pos] = g_dinv[s] * g_dinv[d];
}

// ---------------------------------------------------------------------------
// GEMM: g_hw[N,128] = src @ W[128,128]
//   src = external A (use_agg=0, no relu) or relu(g_agg) (use_agg=1)
// ---------------------------------------------------------------------------
__global__ void __launch_bounds__(256) gemm_relu_k(
    const float* __restrict__ A, const float* __restrict__ W, int use_agg)
{
    __shared__ float As[16][128];
    __shared__ float Bs[16][128];

    const int tid  = threadIdx.x;
    const int row0 = blockIdx.x * 128;
    const int trow = (tid >> 4) * 8;
    const int tcol = (tid & 15) * 8;

    const float* src = use_agg ? g_agg : A;

    float acc[8][8];
#pragma unroll
    for (int m = 0; m < 8; m++)
#pragma unroll
        for (int n = 0; n < 8; n++) acc[m][n] = 0.0f;

    for (int k0 = 0; k0 < 128; k0 += 16) {
#pragma unroll
        for (int t = 0; t < 2; t++) {
            int i  = tid + t * 256;
            int r  = i >> 2;
            int c4 = (i & 3) * 4;
            int grow = row0 + r;
            float4 v = make_float4(0.f, 0.f, 0.f, 0.f);
            if (grow < N_NODES)
                v = *(const float4*)(src + (size_t)grow * DIM + k0 + c4);
            if (use_agg) {
                v.x = fmaxf(v.x, 0.f); v.y = fmaxf(v.y, 0.f);
                v.z = fmaxf(v.z, 0.f); v.w = fmaxf(v.w, 0.f);
            }
            As[c4 + 0][r] = v.x; As[c4 + 1][r] = v.y;
            As[c4 + 2][r] = v.z; As[c4 + 3][r] = v.w;
        }
#pragma unroll
        for (int t = 0; t < 2; t++) {
            int i = tid + t * 256;
            int r = i >> 5;
            int c = (i & 31) * 4;
            *(float4*)&Bs[r][c] = *(const float4*)(W + (size_t)(k0 + r) * DIM + c);
        }
        __syncthreads();

#pragma unroll
        for (int k = 0; k < 16; k++) {
            float a[8], b[8];
#pragma unroll
            for (int m = 0; m < 8; m++) a[m] = As[k][trow + m];
#pragma unroll
            for (int n = 0; n < 8; n++) b[n] = Bs[k][tcol + n];
#pragma unroll
            for (int m = 0; m < 8; m++)
#pragma unroll
                for (int n = 0; n < 8; n++)
                    acc[m][n] += a[m] * b[n];
        }
        __syncthreads();
    }

#pragma unroll
    for (int m = 0; m < 8; m++) {
        int grow = row0 + trow + m;
        if (grow < N_NODES) {
#pragma unroll
            for (int n = 0; n < 8; n += 4) {
                float4 v = make_float4(acc[m][n], acc[m][n + 1],
                                       acc[m][n + 2], acc[m][n + 3]);
                *(float4*)(g_hw + (size_t)grow * DIM + tcol + n) = v;
            }
        }
    }
}

// ---------------------------------------------------------------------------
// gather: one warp per dst node; lane owns float4 #lane of the row.
// acc = bias; acc += hw[src]*norm for each CSR neighbor; write agg (or relu->out)
// ---------------------------------------------------------------------------
__global__ void __launch_bounds__(256) gather_k(
    const float* __restrict__ bias, float* __restrict__ out, int last)
{
    int w    = (blockIdx.x * blockDim.x + threadIdx.x) >> 5;
    int lane = threadIdx.x & 31;
    if (w >= N_NODES) return;

    int beg = g_rowptr[w];
    int end = g_rowptr[w + 1];

    float4 acc = ((const float4*)bias)[lane];
    const float4* hw4 = (const float4*)g_hw;

    int j = beg;
    for (; j + 1 < end; j += 2) {
        int   s0 = g_esrc[j],     s1 = g_esrc[j + 1];
        float n0 = g_enorm[j],    n1 = g_enorm[j + 1];
        float4 v0 = hw4[s0 * 32 + lane];
        float4 v1 = hw4[s1 * 32 + lane];
        acc.x += v0.x * n0; acc.y += v0.y * n0;
        acc.z += v0.z * n0; acc.w += v0.w * n0;
        acc.x += v1.x * n1; acc.y += v1.y * n1;
        acc.z += v1.z * n1; acc.w += v1.w * n1;
    }
    if (j < end) {
        int   s0 = g_esrc[j];
        float n0 = g_enorm[j];
        float4 v0 = hw4[s0 * 32 + lane];
        acc.x += v0.x * n0; acc.y += v0.y * n0;
        acc.z += v0.z * n0; acc.w += v0.w * n0;
    }

    if (last) {
        acc.x = fmaxf(acc.x, 0.f); acc.y = fmaxf(acc.y, 0.f);
        acc.z = fmaxf(acc.z, 0.f); acc.w = fmaxf(acc.w, 0.f);
        ((float4*)out)[w * 32 + lane] = acc;
    } else {
        ((float4*)g_agg)[w * 32 + lane] = acc;
    }
}

// ---------------------------------------------------------------------------
extern "C" void kernel_launch(void* const* d_in, const int* in_sizes, int n_in,
                              void* d_out, int out_size)
{
    const float* x  = (const float*)d_in[0];
    const int*   ei = (const int*)d_in[1];     // edge_index int32 [2, E]
    const float* W0 = (const float*)d_in[2];
    const float* b0 = (const float*)d_in[3];
    const float* W1 = (const float*)d_in[4];
    const float* b1 = (const float*)d_in[5];
    const float* W2 = (const float*)d_in[6];
    const float* b2 = (const float*)d_in[7];
    float* out = (float*)d_out;

    const int edgeBlocks = (N_EDGES + 255) / 256;
    const int totBlocks  = (TOT_EDGES + 255) / 256;
    const int gemmBlocks = (N_NODES + 127) / 128;
    const int gathBlocks = (N_NODES * 32 + 255) / 256;   // warp per node

    // CSR build (once; reused by all 3 layers)
    deg_init_k <<<NB, 256>>>();
    deg_count_k<<<edgeBlocks, 256>>>(ei);
    bsum_k     <<<NB, 256>>>();
    topscan_k  <<<1, 256>>>();
    finalize_k <<<NB, 256>>>();
    fill_k     <<<totBlocks, 256>>>(ei);

    // layer 0
    gemm_relu_k<<<gemmBlocks, 256>>>(x, W0, 0);
    gather_k   <<<gathBlocks, 256>>>(b0, out, 0);
    // layer 1
    gemm_relu_k<<<gemmBlocks, 256>>>(x, W1, 1);
    gather_k   <<<gathBlocks, 256>>>(b1, out, 0);
    // layer 2 (relu fused into final write to d_out)
    gemm_relu_k<<<gemmBlocks, 256>>>(x, W2, 1);
    gather_k   <<<gathBlocks, 256>>>(b2, out, 1);
}

// round 7
// speedup vs baseline: 3.7047x; 1.3397x over previous
#include <cuda_runtime.h>
#include <cstdint>

#define N_NODES 50000
#define N_EDGES 600000
#define DIM 128
#define TOT_EDGES (N_EDGES + N_NODES)   // edges + self loops
#define NB 196                          // ceil(50000/256) scan blocks

// ---- scratch (device globals; no allocations allowed) ----
__device__ float g_hw  [N_NODES * DIM];  // h @ W
__device__ float g_agg [N_NODES * DIM];  // layer output (agg + b)
__device__ float g_dinv[N_NODES];        // rsqrt(deg)
__device__ int   g_deg   [N_NODES];
__device__ int   g_rowptr[N_NODES + 1];
__device__ int   g_cursor[N_NODES];
__device__ int   g_bsum  [NB];
__device__ int   g_esrc  [TOT_EDGES];    // CSR-by-dst: src node per slot
__device__ float g_enorm [TOT_EDGES];    // dinv[src]*dinv[dst] per slot

// ---------------------------------------------------------------------------
// CSR build: degree -> scan -> rowptr/cursor/dinv -> fill
// ---------------------------------------------------------------------------
__global__ void deg_init_k() {
    int i = blockIdx.x * blockDim.x + threadIdx.x;
    if (i < N_NODES) g_deg[i] = 1;          // self loop
}

__global__ void deg_count_k(const int* __restrict__ ei) {
    int e = blockIdx.x * blockDim.x + threadIdx.x;
    if (e < N_EDGES) {
        int d = ei[N_EDGES + e];
        if (d >= 0 && d < N_NODES) atomicAdd(&g_deg[d], 1);
    }
}

__global__ void __launch_bounds__(256) bsum_k() {
    __shared__ int sh[256];
    int i = blockIdx.x * 256 + threadIdx.x;
    sh[threadIdx.x] = (i < N_NODES) ? g_deg[i] : 0;
    __syncthreads();
    for (int off = 128; off > 0; off >>= 1) {
        if (threadIdx.x < off) sh[threadIdx.x] += sh[threadIdx.x + off];
        __syncthreads();
    }
    if (threadIdx.x == 0) g_bsum[blockIdx.x] = sh[0];
}

__global__ void __launch_bounds__(256) topscan_k() {   // exclusive scan of g_bsum
    __shared__ int sh[256];
    int t = threadIdx.x;
    int v = (t < NB) ? g_bsum[t] : 0;
    sh[t] = v;
    __syncthreads();
    for (int off = 1; off < 256; off <<= 1) {
        int x = (t >= off) ? sh[t - off] : 0;
        __syncthreads();
        sh[t] += x;
        __syncthreads();
    }
    if (t < NB) g_bsum[t] = sh[t] - v;      // exclusive
}

__global__ void __launch_bounds__(256) finalize_k() {
    __shared__ int sh[256];
    int i = blockIdx.x * 256 + threadIdx.x;
    int t = threadIdx.x;
    int v = (i < N_NODES) ? g_deg[i] : 0;
    sh[t] = v;
    __syncthreads();
    for (int off = 1; off < 256; off <<= 1) {
        int x = (t >= off) ? sh[t - off] : 0;
        __syncthreads();
        sh[t] += x;
        __syncthreads();
    }
    if (i < N_NODES) {
        int start = g_bsum[blockIdx.x] + sh[t] - v;   // exclusive global
        g_rowptr[i] = start;
        g_cursor[i] = start;
        g_dinv[i]   = rsqrtf((float)v);
        if (i == N_NODES - 1) g_rowptr[N_NODES] = start + v;
    }
}

__global__ void fill_k(const int* __restrict__ ei) {
    int e = blockIdx.x * blockDim.x + threadIdx.x;
    if (e >= TOT_EDGES) return;
    int s, d;
    if (e < N_EDGES) {
        s = ei[e];
        d = ei[N_EDGES + e];
        if (s < 0 || s >= N_NODES || d < 0 || d >= N_NODES) return;
    } else {
        s = d = e - N_EDGES;                // self loop
    }
    int pos = atomicAdd(&g_cursor[d], 1);
    g_esrc[pos]  = s;
    g_enorm[pos] = g_dinv[s] * g_dinv[d];
}

// ---------------------------------------------------------------------------
// tf32 tensor-core GEMM: g_hw[N,128] = src @ W[128,128]
//   src = external A (use_agg=0) or relu(g_agg) (use_agg=1)
// 128x128 block tile, 8 warps (4M x 2N), warp tile 32x64, mma.m16n8k8.tf32
// smem: A chunk [128][36] + W chunk transposed [128n][36k], both padded so
// fragment LDS are bank-conflict-free (4m+k mod 32 covers all banks).
// ---------------------------------------------------------------------------
__device__ __forceinline__ uint32_t f2tf32(float f) {
    uint32_t r;
    asm("cvt.rna.tf32.f32 %0, %1;" : "=r"(r) : "f"(f));
    return r;
}

__global__ void __launch_bounds__(256) gemm_tf32_k(
    const float* __restrict__ A, const float* __restrict__ W, int use_agg)
{
    __shared__ uint32_t As[128 * 36];   // [m][k] chunk, pad 36
    __shared__ uint32_t Wt[128 * 36];   // [n][k] chunk (transposed), pad 36

    const int tid   = threadIdx.x;
    const int lane  = tid & 31;
    const int wid   = tid >> 5;
    const int warpM = wid & 3;          // 0..3  -> 32-row strip
    const int warpN = wid >> 2;         // 0..1  -> 64-col strip
    const int g     = lane >> 2;        // groupID 0..7
    const int q     = lane & 3;         // thread-in-group 0..3
    const int row0  = blockIdx.x * 128;

    const float* src = use_agg ? g_agg : A;

    float acc[2][8][4];
#pragma unroll
    for (int mt = 0; mt < 2; mt++)
#pragma unroll
        for (int nt = 0; nt < 8; nt++)
#pragma unroll
            for (int i = 0; i < 4; i++) acc[mt][nt][i] = 0.0f;

    for (int c = 0; c < 4; ++c) {       // K chunks of 32
        // ---- load A chunk: 128 rows x 32 k (relu + tf32 convert) ----
#pragma unroll
        for (int t = 0; t < 4; t++) {
            int i  = tid + t * 256;     // 0..1023
            int r  = i >> 3;            // 0..127
            int c4 = (i & 7) * 4;       // 0..28
            int grow = row0 + r;
            float4 v = make_float4(0.f, 0.f, 0.f, 0.f);
            if (grow < N_NODES)
                v = *(const float4*)(src + (size_t)grow * DIM + c * 32 + c4);
            if (use_agg) {
                v.x = fmaxf(v.x, 0.f); v.y = fmaxf(v.y, 0.f);
                v.z = fmaxf(v.z, 0.f); v.w = fmaxf(v.w, 0.f);
            }
            uint32_t* p = &As[r * 36 + c4];
            p[0] = f2tf32(v.x); p[1] = f2tf32(v.y);
            p[2] = f2tf32(v.z); p[3] = f2tf32(v.w);
        }
        // ---- load W chunk transposed: Wt[n][k], 32 k-rows x 128 n ----
#pragma unroll
        for (int t = 0; t < 4; t++) {
            int i  = tid + t * 256;     // 0..1023
            int kr = i >> 5;            // 0..31
            int c4 = (i & 31) * 4;      // 0..124
            float4 w = *(const float4*)(W + (size_t)(c * 32 + kr) * DIM + c4);
            Wt[(c4 + 0) * 36 + kr] = f2tf32(w.x);
            Wt[(c4 + 1) * 36 + kr] = f2tf32(w.y);
            Wt[(c4 + 2) * 36 + kr] = f2tf32(w.z);
            Wt[(c4 + 3) * 36 + kr] = f2tf32(w.w);
        }
        __syncthreads();

#pragma unroll
        for (int ks = 0; ks < 4; ++ks) {    // 4 k-steps of 8 within chunk
            const int kk = ks * 8;

            uint32_t a[2][4];
#pragma unroll
            for (int mt = 0; mt < 2; mt++) {
                int mb = warpM * 32 + mt * 16 + g;
                a[mt][0] = As[mb * 36 + kk + q];
                a[mt][1] = As[(mb + 8) * 36 + kk + q];
                a[mt][2] = As[mb * 36 + kk + q + 4];
                a[mt][3] = As[(mb + 8) * 36 + kk + q + 4];
            }
            uint32_t b[8][2];
#pragma unroll
            for (int nt = 0; nt < 8; nt++) {
                int n = warpN * 64 + nt * 8 + g;
                b[nt][0] = Wt[n * 36 + kk + q];
                b[nt][1] = Wt[n * 36 + kk + q + 4];
            }
#pragma unroll
            for (int mt = 0; mt < 2; mt++)
#pragma unroll
                for (int nt = 0; nt < 8; nt++) {
                    asm volatile(
                        "mma.sync.aligned.m16n8k8.row.col.f32.tf32.tf32.f32 "
                        "{%0,%1,%2,%3}, {%4,%5,%6,%7}, {%8,%9}, {%0,%1,%2,%3};"
                        : "+f"(acc[mt][nt][0]), "+f"(acc[mt][nt][1]),
                          "+f"(acc[mt][nt][2]), "+f"(acc[mt][nt][3])
                        : "r"(a[mt][0]), "r"(a[mt][1]), "r"(a[mt][2]), "r"(a[mt][3]),
                          "r"(b[nt][0]), "r"(b[nt][1]));
                }
        }
        __syncthreads();
    }

    // ---- epilogue: c0,c1 -> row g; c2,c3 -> row g+8; cols q*2, q*2+1 ----
#pragma unroll
    for (int mt = 0; mt < 2; mt++) {
        int r0 = row0 + warpM * 32 + mt * 16 + g;
        int r1 = r0 + 8;
#pragma unroll
        for (int nt = 0; nt < 8; nt++) {
            int col = warpN * 64 + nt * 8 + q * 2;
            if (r0 < N_NODES)
                *(float2*)(g_hw + (size_t)r0 * DIM + col) =
                    make_float2(acc[mt][nt][0], acc[mt][nt][1]);
            if (r1 < N_NODES)
                *(float2*)(g_hw + (size_t)r1 * DIM + col) =
                    make_float2(acc[mt][nt][2], acc[mt][nt][3]);
        }
    }
}

// ---------------------------------------------------------------------------
// gather: one warp per dst node; lane owns float4 #lane of the row.
// acc = bias; acc += hw[src]*norm for each CSR neighbor; write agg (or relu->out)
// ---------------------------------------------------------------------------
__global__ void __launch_bounds__(256) gather_k(
    const float* __restrict__ bias, float* __restrict__ out, int last)
{
    int w    = (blockIdx.x * blockDim.x + threadIdx.x) >> 5;
    int lane = threadIdx.x & 31;
    if (w >= N_NODES) return;

    int beg = g_rowptr[w];
    int end = g_rowptr[w + 1];

    float4 acc = ((const float4*)bias)[lane];
    const float4* hw4 = (const float4*)g_hw;

    int j = beg;
    for (; j + 1 < end; j += 2) {
        int   s0 = g_esrc[j],     s1 = g_esrc[j + 1];
        float n0 = g_enorm[j],    n1 = g_enorm[j + 1];
        float4 v0 = hw4[s0 * 32 + lane];
        float4 v1 = hw4[s1 * 32 + lane];
        acc.x += v0.x * n0; acc.y += v0.y * n0;
        acc.z += v0.z * n0; acc.w += v0.w * n0;
        acc.x += v1.x * n1; acc.y += v1.y * n1;
        acc.z += v1.z * n1; acc.w += v1.w * n1;
    }
    if (j < end) {
        int   s0 = g_esrc[j];
        float n0 = g_enorm[j];
        float4 v0 = hw4[s0 * 32 + lane];
        acc.x += v0.x * n0; acc.y += v0.y * n0;
        acc.z += v0.z * n0; acc.w += v0.w * n0;
    }

    if (last) {
        acc.x = fmaxf(acc.x, 0.f); acc.y = fmaxf(acc.y, 0.f);
        acc.z = fmaxf(acc.z, 0.f); acc.w = fmaxf(acc.w, 0.f);
        ((float4*)out)[w * 32 + lane] = acc;
    } else {
        ((float4*)g_agg)[w * 32 + lane] = acc;
    }
}

// ---------------------------------------------------------------------------
extern "C" void kernel_launch(void* const* d_in, const int* in_sizes, int n_in,
                              void* d_out, int out_size)
{
    const float* x  = (const float*)d_in[0];
    const int*   ei = (const int*)d_in[1];     // edge_index int32 [2, E]
    const float* W0 = (const float*)d_in[2];
    const float* b0 = (const float*)d_in[3];
    const float* W1 = (const float*)d_in[4];
    const float* b1 = (const float*)d_in[5];
    const float* W2 = (const float*)d_in[6];
    const float* b2 = (const float*)d_in[7];
    float* out = (float*)d_out;

    const int edgeBlocks = (N_EDGES + 255) / 256;
    const int totBlocks  = (TOT_EDGES + 255) / 256;
    const int gemmBlocks = (N_NODES + 127) / 128;
    const int gathBlocks = (N_NODES * 32 + 255) / 256;   // warp per node

    // CSR build (once; reused by all 3 layers)
    deg_init_k <<<NB, 256>>>();
    deg_count_k<<<edgeBlocks, 256>>>(ei);
    bsum_k     <<<NB, 256>>>();
    topscan_k  <<<1, 256>>>();
    finalize_k <<<NB, 256>>>();
    fill_k     <<<totBlocks, 256>>>(ei);

    // layer 0
    gemm_tf32_k<<<gemmBlocks, 256>>>(x, W0, 0);
    gather_k   <<<gathBlocks, 256>>>(b0, out, 0);
    // layer 1
    gemm_tf32_k<<<gemmBlocks, 256>>>(x, W1, 1);
    gather_k   <<<gathBlocks, 256>>>(b1, out, 0);
    // layer 2 (relu fused into final write to d_out)
    gemm_tf32_k<<<gemmBlocks, 256>>>(x, W2, 1);
    gather_k   <<<gathBlocks, 256>>>(b2, out, 1);
}